// round 1
// baseline (speedup 1.0000x reference)
#include <cuda_runtime.h>
#include <math.h>

#define NB   64
#define TT   64
#define VV   25
#define DIMC 384
#define HH   6
#define HD   64
#define TV   1600                 // T*V
#define SL   39321600             // N*T*H*HD*V  (per-slot scratch size)

// Scratch: slots 0..4 = K, V, Q, EK, EQ, each [N,T,H,HD,V] fp32
__device__ float g_proj[5u * SL];

// ---------------- packed f32x2 helpers ----------------
__device__ __forceinline__ unsigned long long pack2(float lo, float hi) {
    unsigned long long r;
    asm("mov.b64 %0, {%1, %2};" : "=l"(r) : "f"(lo), "f"(hi));
    return r;
}
__device__ __forceinline__ void unpack2(unsigned long long a, float& lo, float& hi) {
    asm("mov.b64 {%0, %1}, %2;" : "=f"(lo), "=f"(hi) : "l"(a));
}
__device__ __forceinline__ unsigned long long fma2(unsigned long long a,
                                                   unsigned long long b,
                                                   unsigned long long c) {
    unsigned long long d;
    asm("fma.rn.f32x2 %0, %1, %2, %3;" : "=l"(d) : "l"(a), "l"(b), "l"(c));
    return d;
}

// =====================================================================
// Kernel A: projection GEMM.
// path 0: W = [kv_w(768); q_w(384)]  @ x[n]  -> slots K(0), V(1), Q(2)
// path 1: W = [e_kv_w[0:384]; e_q_w] @ e[n]  -> slots EK(3), EQ(4)
// C tile 64(o) x 128(p), K-tile 16, 256 threads, 4x8 micro-tile via f32x2.
// =====================================================================
__global__ __launch_bounds__(256) void proj_gemm(
    const float* __restrict__ x, const float* __restrict__ e,
    const float* __restrict__ kv_w, const float* __restrict__ q_w,
    const float* __restrict__ e_kv_w, const float* __restrict__ e_q_w)
{
    const int n    = blockIdx.z & 63;
    const int path = blockIdx.z >> 6;
    const int by   = blockIdx.y;
    if (path == 1 && by >= 12) return;

    const int o0 = by * 64;
    const int p0 = blockIdx.x * 128;

    const float* X = (path ? e : x) + (size_t)n * DIMC * TV;
    const float* W;
    if (path == 0) W = (o0 < 768) ? (kv_w + (size_t)o0 * DIMC) : (q_w + (size_t)(o0 - 768) * DIMC);
    else           W = (o0 < 384) ? (e_kv_w + (size_t)o0 * DIMC) : (e_q_w + (size_t)(o0 - 384) * DIMC);

    __shared__ float Ws[16][68];   // [k][o], padded
    __shared__ float Xs[16][128];  // [k][p]

    const int tid = threadIdx.x;
    const int to  = tid >> 4;      // 0..15 -> o base = to*4
    const int tp  = tid & 15;      // 0..15 -> p base = tp*8

    unsigned long long acc2[4][4];
#pragma unroll
    for (int i = 0; i < 4; i++)
#pragma unroll
        for (int j = 0; j < 4; j++) acc2[i][j] = 0ull;

    for (int k0 = 0; k0 < DIMC; k0 += 16) {
        // W tile 64x16 : each thread one float4 along k
        {
            int o_l = tid >> 2;
            int kk  = (tid & 3) << 2;
            float4 w4 = *reinterpret_cast<const float4*>(W + (size_t)o_l * DIMC + k0 + kk);
            Ws[kk + 0][o_l] = w4.x;
            Ws[kk + 1][o_l] = w4.y;
            Ws[kk + 2][o_l] = w4.z;
            Ws[kk + 3][o_l] = w4.w;
        }
        // X tile 16x128 : two float4 per thread, coalesced along p
#pragma unroll
        for (int i = 0; i < 2; i++) {
            int f = tid + 256 * i;
            int r = f >> 5;
            int c = (f & 31) << 2;
            float4 v4 = make_float4(0.f, 0.f, 0.f, 0.f);
            if (p0 + c < TV)
                v4 = *reinterpret_cast<const float4*>(X + (size_t)(k0 + r) * TV + p0 + c);
            *reinterpret_cast<float4*>(&Xs[r][c]) = v4;
        }
        __syncthreads();

#pragma unroll
        for (int k = 0; k < 16; k++) {
            float4 wv = *reinterpret_cast<const float4*>(&Ws[k][to * 4]);
            const unsigned long long* xr =
                reinterpret_cast<const unsigned long long*>(&Xs[k][tp * 8]);
            unsigned long long xp0 = xr[0], xp1 = xr[1], xp2 = xr[2], xp3 = xr[3];
            unsigned long long w0 = pack2(wv.x, wv.x);
            unsigned long long w1 = pack2(wv.y, wv.y);
            unsigned long long w2 = pack2(wv.z, wv.z);
            unsigned long long w3 = pack2(wv.w, wv.w);
            acc2[0][0] = fma2(w0, xp0, acc2[0][0]);
            acc2[0][1] = fma2(w0, xp1, acc2[0][1]);
            acc2[0][2] = fma2(w0, xp2, acc2[0][2]);
            acc2[0][3] = fma2(w0, xp3, acc2[0][3]);
            acc2[1][0] = fma2(w1, xp0, acc2[1][0]);
            acc2[1][1] = fma2(w1, xp1, acc2[1][1]);
            acc2[1][2] = fma2(w1, xp2, acc2[1][2]);
            acc2[1][3] = fma2(w1, xp3, acc2[1][3]);
            acc2[2][0] = fma2(w2, xp0, acc2[2][0]);
            acc2[2][1] = fma2(w2, xp1, acc2[2][1]);
            acc2[2][2] = fma2(w2, xp2, acc2[2][2]);
            acc2[2][3] = fma2(w2, xp3, acc2[2][3]);
            acc2[3][0] = fma2(w3, xp0, acc2[3][0]);
            acc2[3][1] = fma2(w3, xp1, acc2[3][1]);
            acc2[3][2] = fma2(w3, xp2, acc2[3][2]);
            acc2[3][3] = fma2(w3, xp3, acc2[3][3]);
        }
        __syncthreads();
    }

    // scatter-store to [slot][N,T,H,HD,V]
#pragma unroll
    for (int ii = 0; ii < 4; ii++) {
        int o_g = o0 + to * 4 + ii;
        int slot, rem;
        if (path == 0) { slot = o_g / 384;     rem = o_g % 384; }
        else           { slot = 3 + o_g / 384; rem = o_g % 384; }
        int hh = rem >> 6, dd = rem & 63;
        size_t obase = (size_t)slot * SL
                     + ((((size_t)n * TT) * HH + hh) * HD + dd) * VV;
        // note: t term added per element below
#pragma unroll
        for (int jj = 0; jj < 4; jj++) {
            float lo, hi;
            unpack2(acc2[ii][jj], lo, hi);
            int p = p0 + tp * 8 + jj * 2;
            if (p < TV) {
                int t = p / 25, v = p % 25;
                g_proj[obase + (size_t)t * (HH * HD * VV) + v] = lo;
            }
            p++;
            if (p < TV) {
                int t = p / 25, v = p % 25;
                g_proj[obase + (size_t)t * (HH * HD * VV) + v] = hi;
            }
        }
    }
}

// =====================================================================
// Kernel B: attention + fused grouped projection. One block per (n,t,h).
// =====================================================================
__global__ __launch_bounds__(128) void attn_kernel(
    const float* __restrict__ rpe, const float* __restrict__ outer,
    const float* __restrict__ alpha_p, const float* __restrict__ beta_p,
    const float* __restrict__ proj_w, const float* __restrict__ proj_b,
    const int* __restrict__ hops, int nh,
    float* __restrict__ xo_out, float* __restrict__ eo_out)
{
    const int h = blockIdx.x, t = blockIdx.y, n = blockIdx.z;
    const int tid = threadIdx.x;

    __shared__ float sm[10600];
    __shared__ unsigned char shops[640];

    const int P = 68;
    const int OQ = 0, OEQ = 1700, OEK = 3400, OKE = 5100, OV = 6800;
    const int OS = 8500, OD = 9200, OQR = 9900;
    const int OXO = OKE;   // reused after scores
    const int OW  = 0;     // reused (Q/EQ/part of EK) for 64x64 proj weights

    const size_t base = (((size_t)n * TT + t) * HH + h) * (size_t)(HD * VV);

    // ---- load tiles (global layout [d][v]; smem layout [v][d], pitch 68) ----
    for (int l = tid; l < 1600; l += 128) {
        int d = l / 25, v = l % 25;
        float kk = g_proj[0 * (size_t)SL + base + l];
        float vv = g_proj[1 * (size_t)SL + base + l];
        float qq = g_proj[2 * (size_t)SL + base + l];
        float ek = g_proj[3 * (size_t)SL + base + l];
        float eq = g_proj[4 * (size_t)SL + base + l];
        sm[OQ  + v * P + d] = qq;
        sm[OEQ + v * P + d] = eq;
        sm[OEK + v * P + d] = ek;
        sm[OKE + v * P + d] = kk + ek;   // q·(k+ek) = a + c
        sm[OV  + v * P + d] = vv;
    }
    for (int l = tid; l < 625; l += 128) shops[l] = (unsigned char)hops[l];
    __syncthreads();

    // ---- qR[i][hop] = q_i · rpe[hop, h*64:...] (rpe from L2) ----
    for (int l = tid; l < 25 * nh; l += 128) {
        int i = l / nh, hp = l % nh;
        const float* rr = rpe + (size_t)hp * DIMC + h * HD;
        const float* qi = &sm[OQ + i * P];
        float acc = 0.f;
#pragma unroll
        for (int d = 0; d < 64; d += 4) {
            float4 q4 = *reinterpret_cast<const float4*>(qi + d);
            float4 r4 = *reinterpret_cast<const float4*>(rr + d);
            acc += q4.x * r4.x + q4.y * r4.y + q4.z * r4.z + q4.w * r4.w;
        }
        sm[OQR + i * 28 + hp] = acc;
    }
    __syncthreads();

    // ---- scores: S = q·(k+ek) + eq·ek + b ; D = eq·ek (1 i x 5 j tile) ----
    if (tid < 125) {
        int i = tid / 5, jg = tid % 5;
        float s1[5] = {0, 0, 0, 0, 0};
        float s2[5] = {0, 0, 0, 0, 0};
        const float* qi  = &sm[OQ  + i * P];
        const float* eqi = &sm[OEQ + i * P];
#pragma unroll
        for (int d = 0; d < 64; d += 4) {
            float4 q4 = *reinterpret_cast<const float4*>(qi + d);
            float4 e4 = *reinterpret_cast<const float4*>(eqi + d);
#pragma unroll
            for (int jj = 0; jj < 5; jj++) {
                int j = jg * 5 + jj;
                float4 k4 = *reinterpret_cast<const float4*>(&sm[OKE + j * P + d]);
                float4 x4 = *reinterpret_cast<const float4*>(&sm[OEK + j * P + d]);
                s1[jj] += q4.x * k4.x + q4.y * k4.y + q4.z * k4.z + q4.w * k4.w;
                s2[jj] += e4.x * x4.x + e4.y * x4.y + e4.z * x4.z + e4.w * x4.w;
            }
        }
#pragma unroll
        for (int jj = 0; jj < 5; jj++) {
            int j = jg * 5 + jj;
            float b = sm[OQR + i * 28 + shops[i * 25 + j]];
            sm[OS + i * 28 + j] = s1[jj] + s2[jj] + b;
            sm[OD + i * 28 + j] = s2[jj];
        }
    }
    __syncthreads();

    // ---- outer -> OQR (qR is dead now) ----
    for (int l = tid; l < 625; l += 128)
        sm[OQR + (l / 25) * 28 + (l % 25)] = outer[(size_t)h * 625 + l];
    __syncthreads();

    const float alpha = __ldg(alpha_p);
    const float beta  = __ldg(beta_p);
    const float scale = 0.125f;   // HD^-0.5

    // ---- softmax (50 rows: 25 for S, 25 for D), then fold alpha/outer/beta ----
    if (tid < 50) {
        int i = tid % 25;
        float* row = &sm[(tid < 25 ? OS : OD) + i * 28];
        float m = -1e30f;
#pragma unroll
        for (int j = 0; j < 25; j++) m = fmaxf(m, row[j]);
        float ebuf[25];
        float s = 0.f;
#pragma unroll
        for (int j = 0; j < 25; j++) { float v = expf((row[j] - m) * scale); ebuf[j] = v; s += v; }
        float inv = 1.f / s;
        if (tid < 25) {
#pragma unroll
            for (int j = 0; j < 25; j++)
                row[j] = alpha * (ebuf[j] * inv) + sm[OQR + i * 28 + j];
        } else {
#pragma unroll
            for (int j = 0; j < 25; j++)
                row[j] = beta * (ebuf[j] * inv);
        }
    }
    __syncthreads();

    // ---- AV for xo (to smem) and eo (to gmem), 5i x 4d tile per thread ----
    if (tid < 80) {
        int ig = tid / 16;   // i = ig*5 + ii
        int dg = tid % 16;   // d = dg*4 + dd
        float aX[5][4], aE[5][4];
#pragma unroll
        for (int ii = 0; ii < 5; ii++)
#pragma unroll
            for (int dd = 0; dd < 4; dd++) { aX[ii][dd] = 0.f; aE[ii][dd] = 0.f; }
#pragma unroll
        for (int j = 0; j < 25; j++) {
            float4 v4 = *reinterpret_cast<const float4*>(&sm[OV + j * P + dg * 4]);
#pragma unroll
            for (int ii = 0; ii < 5; ii++) {
                float a  = sm[OS + (ig * 5 + ii) * 28 + j];
                float dc = sm[OD + (ig * 5 + ii) * 28 + j];
                aX[ii][0] += a * v4.x;  aX[ii][1] += a * v4.y;
                aX[ii][2] += a * v4.z;  aX[ii][3] += a * v4.w;
                aE[ii][0] += dc * v4.x; aE[ii][1] += dc * v4.y;
                aE[ii][2] += dc * v4.z; aE[ii][3] += dc * v4.w;
            }
        }
#pragma unroll
        for (int ii = 0; ii < 5; ii++) {
            int i = ig * 5 + ii;
#pragma unroll
            for (int dd = 0; dd < 4; dd++) {
                int d = dg * 4 + dd;
                eo_out[(((size_t)n * DIMC + h * HD + d) * TT + t) * VV + i] = aE[ii][dd];
                sm[OXO + i * P + d] = aX[ii][dd];
            }
        }
    }
    // load proj weights for this head into smem [o][c] (region reuse; no reader conflicts)
    for (int l = tid; l < 4096; l += 128)
        sm[OW + l] = proj_w[(size_t)h * 4096 + l];
    __syncthreads();

    // ---- grouped projection: out[i][o] = xo[i][:] · W[o][:] + b, 5i x 4o tile ----
    if (tid < 80) {
        int ig = tid / 16;   // i = ig*5 + ii
        int og = tid % 16;   // o = og*4 + oo
        float acc[5][4];
#pragma unroll
        for (int ii = 0; ii < 5; ii++)
#pragma unroll
            for (int oo = 0; oo < 4; oo++) acc[ii][oo] = 0.f;
#pragma unroll
        for (int c = 0; c < 64; c += 4) {
            float4 w4[4];
#pragma unroll
            for (int oo = 0; oo < 4; oo++)
                w4[oo] = *reinterpret_cast<const float4*>(&sm[OW + (og * 4 + oo) * 64 + c]);
#pragma unroll
            for (int ii = 0; ii < 5; ii++) {
                float4 x4 = *reinterpret_cast<const float4*>(&sm[OXO + (ig * 5 + ii) * P + c]);
#pragma unroll
                for (int oo = 0; oo < 4; oo++)
                    acc[ii][oo] += x4.x * w4[oo].x + x4.y * w4[oo].y
                                 + x4.z * w4[oo].z + x4.w * w4[oo].w;
            }
        }
#pragma unroll
        for (int oo = 0; oo < 4; oo++) {
            int o = og * 4 + oo;
            float b = __ldg(proj_b + h * HD + o);
#pragma unroll
            for (int ii = 0; ii < 5; ii++) {
                int i = ig * 5 + ii;
                xo_out[(((size_t)n * DIMC + h * HD + o) * TT + t) * VV + i] = acc[ii][oo] + b;
            }
        }
    }
}

extern "C" void kernel_launch(void* const* d_in, const int* in_sizes, int n_in,
                              void* d_out, int out_size)
{
    const float* x      = (const float*)d_in[0];
    const float* e      = (const float*)d_in[1];
    const float* kv_w   = (const float*)d_in[2];
    const float* q_w    = (const float*)d_in[3];
    const float* e_kv_w = (const float*)d_in[4];
    const float* e_q_w  = (const float*)d_in[5];
    const float* rpe    = (const float*)d_in[6];
    const float* outerp = (const float*)d_in[7];
    const float* alpha  = (const float*)d_in[8];
    const float* beta   = (const float*)d_in[9];
    const float* proj_w = (const float*)d_in[10];
    const float* proj_b = (const float*)d_in[11];
    const int*   hops   = (const int*)d_in[12];

    int nh = in_sizes[6] / DIMC;

    float* xo = (float*)d_out;
    float* eo = xo + (size_t)NB * DIMC * TT * VV;

    proj_gemm<<<dim3(13, 18, 128), 256>>>(x, e, kv_w, q_w, e_kv_w, e_q_w);
    attn_kernel<<<dim3(HH, TT, NB), 128>>>(rpe, outerp, alpha, beta,
                                           proj_w, proj_b, hops, nh, xo, eo);
}

// round 6
// speedup vs baseline: 2.0306x; 2.0306x over previous
#include <cuda_runtime.h>
#include <cuda_bf16.h>
#include <math.h>
#include <stdint.h>

#define NB   64
#define TT   64
#define VV   25
#define DIMC 384
#define HH   6
#define HD   64
#define TV   1600                 // T*V
#define SL   39321600             // N*T*H*HD*V  (per-slot scratch size)
#define NSTRIDE 614400u           // T*H*HD*V    (per-n stride within a slot)

// Scratch: slots 0..4 = K, V, Q, EK, EQ, each [N,T,H,HD,V] fp32
__device__ float g_proj[5u * SL];

// ---------------- helpers ----------------
__device__ __forceinline__ uint32_t smem_u32(const void* p) {
    uint32_t a;
    asm("{ .reg .u64 t; cvta.to.shared.u64 t, %1; cvt.u32.u64 %0, t; }"
        : "=r"(a) : "l"(p));
    return a;
}
__device__ __forceinline__ void split4(float4 v, uint2& h, uint2& l) {
    __nv_bfloat162 h0 = __floats2bfloat162_rn(v.x, v.y);
    __nv_bfloat162 h1 = __floats2bfloat162_rn(v.z, v.w);
    float2 f0 = __bfloat1622float2(h0);
    float2 f1 = __bfloat1622float2(h1);
    __nv_bfloat162 l0 = __floats2bfloat162_rn(v.x - f0.x, v.y - f0.y);
    __nv_bfloat162 l1 = __floats2bfloat162_rn(v.z - f1.x, v.w - f1.y);
    h = make_uint2(*(uint32_t*)&h0, *(uint32_t*)&h1);
    l = make_uint2(*(uint32_t*)&l0, *(uint32_t*)&l1);
}
__device__ __forceinline__ void ldsm4(uint32_t addr, uint32_t* r) {
    asm volatile("ldmatrix.sync.aligned.m8n8.x4.shared.b16 {%0,%1,%2,%3}, [%4];"
                 : "=r"(r[0]), "=r"(r[1]), "=r"(r[2]), "=r"(r[3]) : "r"(addr));
}
__device__ __forceinline__ void ldsm4t(uint32_t addr, uint32_t* r) {
    asm volatile("ldmatrix.sync.aligned.m8n8.x4.trans.shared.b16 {%0,%1,%2,%3}, [%4];"
                 : "=r"(r[0]), "=r"(r[1]), "=r"(r[2]), "=r"(r[3]) : "r"(addr));
}
__device__ __forceinline__ void mma_bf16(float* c, const uint32_t* a, const uint32_t* b) {
    asm volatile("mma.sync.aligned.m16n8k16.row.col.f32.bf16.bf16.f32 "
                 "{%0,%1,%2,%3}, {%4,%5,%6,%7}, {%8,%9}, {%0,%1,%2,%3};"
                 : "+f"(c[0]), "+f"(c[1]), "+f"(c[2]), "+f"(c[3])
                 : "r"(a[0]), "r"(a[1]), "r"(a[2]), "r"(a[3]), "r"(b[0]), "r"(b[1]));
}

// =====================================================================
// Projection GEMM via mma.sync bf16 (Markidis 3-split, fp32-grade).
// CTA tile: M=128 (channels) x N=128 (positions of T*V), K=384, BK=32.
// A = W (K-major), B = X tile ([k][p] -> ldmatrix.trans).
// grid: x = 13 n-tiles, y = 15 m-tiles, z = 64 batch.
// =====================================================================
#define A_PITCH 80              // bytes per m-row (32 bf16 + pad), 5*16
#define B_PITCH 272             // bytes per k-row (128 bf16 + pad), 17*16
#define A_BYTES (128 * A_PITCH) // 10240
#define B_BYTES (32 * B_PITCH)  // 8704
#define STAGE_BYTES (2 * A_BYTES + 2 * B_BYTES)  // AHI,ALO,BHI,BLO = 37888
#define DYN_BYTES (2 * STAGE_BYTES)              // 75776

__global__ __launch_bounds__(256, 1)
void proj_mma(const float* __restrict__ x, const float* __restrict__ e,
              const float* __restrict__ kv_w, const float* __restrict__ q_w,
              const float* __restrict__ e_kv_w, const float* __restrict__ e_q_w)
{
    const int nt  = blockIdx.x;     // 0..12
    const int mt  = blockIdx.y;     // 0..14
    const int n   = blockIdx.z;     // 0..63
    const int tid = threadIdx.x;
    const int lane = tid & 31;
    const int w    = tid >> 5;
    const int wm   = w & 3;         // m-warp 0..3 (rows wm*32)
    const int wn   = w >> 2;        // n-warp 0..1 (cols wn*64)

    extern __shared__ char smem[];
    const uint32_t smem_b = smem_u32(smem);

    const float* Wsrc; int path, o_origin;
    if      (mt < 6)  { Wsrc = kv_w   + (size_t)mt * 128 * DIMC;        path = 0; o_origin = mt * 128; }
    else if (mt < 9)  { Wsrc = q_w    + (size_t)(mt - 6) * 128 * DIMC;  path = 0; o_origin = mt * 128; }
    else if (mt < 12) { Wsrc = e_kv_w + (size_t)(mt - 9) * 128 * DIMC;  path = 1; o_origin = (mt - 9) * 128; }
    else              { Wsrc = e_q_w  + (size_t)(mt - 12) * 128 * DIMC; path = 1; o_origin = 384 + (mt - 12) * 128; }
    const float* Xn = (path ? e : x) + (size_t)n * DIMC * TV;
    const int p0 = nt * 128;

    // ---- per-thread load/store indices ----
    const int a_r  = tid >> 3;          // A row 0..31 (+32*i)
    const int a_c4 = tid & 7;           // float4 index within 32-k row
    const int b_k  = tid >> 5;          // B k-row 0..7 (+8*i)
    const int b_p  = (tid & 31) * 4;    // local p (float4)
    const bool b_ok = (p0 + b_p) < TV;

    float4 pa[4], pb[4];

    // ---- ldmatrix per-lane addresses (byte offsets within stage) ----
    const uint32_t aoff = (uint32_t)((wm * 32 + (lane & 15)) * A_PITCH + (lane >> 4) * 16);
    const uint32_t boff = (uint32_t)((lane & 15) * B_PITCH + (wn * 64 + (lane >> 4) * 8) * 2);

    float acc[16][4];
#pragma unroll
    for (int i = 0; i < 16; i++)
#pragma unroll
        for (int j = 0; j < 4; j++) acc[i][j] = 0.f;

    // ---- prologue: load + store chunk 0 ----
#pragma unroll
    for (int i = 0; i < 4; i++) {
        pa[i] = *(const float4*)(Wsrc + (size_t)(a_r + 32 * i) * DIMC + a_c4 * 4);
        pb[i] = b_ok ? *(const float4*)(Xn + (size_t)(b_k + 8 * i) * TV + p0 + b_p)
                     : make_float4(0.f, 0.f, 0.f, 0.f);
    }
    {
        char* st = smem;
#pragma unroll
        for (int i = 0; i < 4; i++) {
            uint2 h, l; split4(pa[i], h, l);
            uint32_t o = (uint32_t)((a_r + 32 * i) * A_PITCH + a_c4 * 8);
            *(uint2*)(st + o) = h;
            *(uint2*)(st + A_BYTES + o) = l;
            split4(pb[i], h, l);
            o = (uint32_t)((b_k + 8 * i) * B_PITCH + b_p * 2);
            *(uint2*)(st + 2 * A_BYTES + o) = h;
            *(uint2*)(st + 2 * A_BYTES + B_BYTES + o) = l;
        }
    }
    __syncthreads();

    for (int c = 0; c < 12; ++c) {
        if (c < 11) {
            const int k0 = (c + 1) * 32;
#pragma unroll
            for (int i = 0; i < 4; i++) {
                pa[i] = *(const float4*)(Wsrc + (size_t)(a_r + 32 * i) * DIMC + k0 + a_c4 * 4);
                pb[i] = b_ok ? *(const float4*)(Xn + (size_t)(k0 + b_k + 8 * i) * TV + p0 + b_p)
                             : make_float4(0.f, 0.f, 0.f, 0.f);
            }
        }

        // ---- compute from buffer c&1 ----
        {
            const uint32_t stage = smem_b + (uint32_t)((c & 1) * STAGE_BYTES);
            const uint32_t aHi = stage + aoff;
            const uint32_t aLo = aHi + A_BYTES;
            const uint32_t bHi = stage + 2 * A_BYTES + boff;
            const uint32_t bLo = bHi + B_BYTES;
#pragma unroll
            for (int s = 0; s < 2; s++) {
                uint32_t Ah[2][4], Al[2][4];
#pragma unroll
                for (int m = 0; m < 2; m++) {
                    ldsm4(aHi + m * 16 * A_PITCH + s * 32, Ah[m]);
                    ldsm4(aLo + m * 16 * A_PITCH + s * 32, Al[m]);
                }
                uint32_t Bh[4][4], Bl[4][4];
#pragma unroll
                for (int g = 0; g < 4; g++) {
                    ldsm4t(bHi + s * 16 * B_PITCH + g * 32, Bh[g]);
                    ldsm4t(bLo + s * 16 * B_PITCH + g * 32, Bl[g]);
                }
#pragma unroll
                for (int m = 0; m < 2; m++)
#pragma unroll
                    for (int g = 0; g < 4; g++)
#pragma unroll
                        for (int half = 0; half < 2; half++) {
                            float* cc = acc[m * 8 + g * 2 + half];
                            mma_bf16(cc, Ah[m], &Bh[g][half * 2]);
                            mma_bf16(cc, Ah[m], &Bl[g][half * 2]);
                            mma_bf16(cc, Al[m], &Bh[g][half * 2]);
                        }
            }
        }

        if (c < 11) {
            char* st = smem + ((c + 1) & 1) * STAGE_BYTES;
#pragma unroll
            for (int i = 0; i < 4; i++) {
                uint2 h, l; split4(pa[i], h, l);
                uint32_t o = (uint32_t)((a_r + 32 * i) * A_PITCH + a_c4 * 8);
                *(uint2*)(st + o) = h;
                *(uint2*)(st + A_BYTES + o) = l;
                split4(pb[i], h, l);
                o = (uint32_t)((b_k + 8 * i) * B_PITCH + b_p * 2);
                *(uint2*)(st + 2 * A_BYTES + o) = h;
                *(uint2*)(st + 2 * A_BYTES + B_BYTES + o) = l;
            }
            __syncthreads();
        }
    }

    // ---- epilogue: scatter C to g_proj ----
    // Fragment map (m16n8k16): c0:(row g, col tig*2) c1:(g, tig*2+1)
    //                          c2:(g+8, tig*2)       c3:(g+8, tig*2+1)
    // acc[m*8 + ntile] covers rows wm*32+m*16..+15, cols wn*64+ntile*8..+7
    const int g   = lane >> 2;
    const int tig = lane & 3;
#pragma unroll
    for (int m = 0; m < 2; m++) {
#pragma unroll
        for (int ntile = 0; ntile < 8; ntile++) {
#pragma unroll
            for (int j = 0; j < 4; j++) {
                int o_g = o_origin + wm * 32 + m * 16 + g + (j >> 1) * 8;
                uint32_t p = (uint32_t)(p0 + wn * 64 + ntile * 8 + tig * 2 + (j & 1));
                if (p < TV) {
                    int cdiv = o_g / 384;
                    int slot = cdiv + (path ? 3 : 0);
                    int rem  = o_g - cdiv * 384;
                    int hh = rem >> 6, dd = rem & 63;
                    uint32_t t = (p * 5243u) >> 17;
                    uint32_t v = p - t * 25u;
                    uint32_t addr = (uint32_t)slot * (uint32_t)SL + (uint32_t)n * NSTRIDE
                                  + t * 9600u + (uint32_t)hh * 1600u + (uint32_t)dd * 25u + v;
                    g_proj[addr] = acc[m * 8 + ntile][j];
                }
            }
        }
    }
}

// =====================================================================
// Kernel B: attention + fused grouped projection. One block per (n,t,h).
// =====================================================================
__global__ __launch_bounds__(128) void attn_kernel(
    const float* __restrict__ rpe, const float* __restrict__ outer,
    const float* __restrict__ alpha_p, const float* __restrict__ beta_p,
    const float* __restrict__ proj_w, const float* __restrict__ proj_b,
    const int* __restrict__ hops, int nh,
    float* __restrict__ xo_out, float* __restrict__ eo_out)
{
    const int h = blockIdx.x, t = blockIdx.y, n = blockIdx.z;
    const int tid = threadIdx.x;

    __shared__ float sm[10600];
    __shared__ unsigned char shops[640];

    const int P = 68;
    const int OQ = 0, OEQ = 1700, OEK = 3400, OKE = 5100, OV = 6800;
    const int OS = 8500, OD = 9200, OQR = 9900;
    const int OXO = OKE;
    const int OW  = 0;

    const size_t base = (((size_t)n * TT + t) * HH + h) * (size_t)(HD * VV);

    for (int l = tid; l < 1600; l += 128) {
        int d = l / 25, v = l % 25;
        float kk = g_proj[0 * (size_t)SL + base + l];
        float vv = g_proj[1 * (size_t)SL + base + l];
        float qq = g_proj[2 * (size_t)SL + base + l];
        float ek = g_proj[3 * (size_t)SL + base + l];
        float eq = g_proj[4 * (size_t)SL + base + l];
        sm[OQ  + v * P + d] = qq;
        sm[OEQ + v * P + d] = eq;
        sm[OEK + v * P + d] = ek;
        sm[OKE + v * P + d] = kk + ek;
        sm[OV  + v * P + d] = vv;
    }
    for (int l = tid; l < 625; l += 128) shops[l] = (unsigned char)hops[l];
    __syncthreads();

    for (int l = tid; l < 25 * nh; l += 128) {
        int i = l / nh, hp = l % nh;
        const float* rr = rpe + (size_t)hp * DIMC + h * HD;
        const float* qi = &sm[OQ + i * P];
        float acc = 0.f;
#pragma unroll
        for (int d = 0; d < 64; d += 4) {
            float4 q4 = *reinterpret_cast<const float4*>(qi + d);
            float4 r4 = *reinterpret_cast<const float4*>(rr + d);
            acc += q4.x * r4.x + q4.y * r4.y + q4.z * r4.z + q4.w * r4.w;
        }
        sm[OQR + i * 28 + hp] = acc;
    }
    __syncthreads();

    if (tid < 125) {
        int i = tid / 5, jg = tid % 5;
        float s1[5] = {0, 0, 0, 0, 0};
        float s2[5] = {0, 0, 0, 0, 0};
        const float* qi  = &sm[OQ  + i * P];
        const float* eqi = &sm[OEQ + i * P];
#pragma unroll
        for (int d = 0; d < 64; d += 4) {
            float4 q4 = *reinterpret_cast<const float4*>(qi + d);
            float4 e4 = *reinterpret_cast<const float4*>(eqi + d);
#pragma unroll
            for (int jj = 0; jj < 5; jj++) {
                int j = jg * 5 + jj;
                float4 k4 = *reinterpret_cast<const float4*>(&sm[OKE + j * P + d]);
                float4 x4 = *reinterpret_cast<const float4*>(&sm[OEK + j * P + d]);
                s1[jj] += q4.x * k4.x + q4.y * k4.y + q4.z * k4.z + q4.w * k4.w;
                s2[jj] += e4.x * x4.x + e4.y * x4.y + e4.z * x4.z + e4.w * x4.w;
            }
        }
#pragma unroll
        for (int jj = 0; jj < 5; jj++) {
            int j = jg * 5 + jj;
            float b = sm[OQR + i * 28 + shops[i * 25 + j]];
            sm[OS + i * 28 + j] = s1[jj] + s2[jj] + b;
            sm[OD + i * 28 + j] = s2[jj];
        }
    }
    __syncthreads();

    for (int l = tid; l < 625; l += 128)
        sm[OQR + (l / 25) * 28 + (l % 25)] = outer[(size_t)h * 625 + l];
    __syncthreads();

    const float alpha = __ldg(alpha_p);
    const float beta  = __ldg(beta_p);
    const float scale = 0.125f;

    if (tid < 50) {
        int i = tid % 25;
        float* row = &sm[(tid < 25 ? OS : OD) + i * 28];
        float m = -1e30f;
#pragma unroll
        for (int j = 0; j < 25; j++) m = fmaxf(m, row[j]);
        float ebuf[25];
        float s = 0.f;
#pragma unroll
        for (int j = 0; j < 25; j++) { float v = expf((row[j] - m) * scale); ebuf[j] = v; s += v; }
        float inv = 1.f / s;
        if (tid < 25) {
#pragma unroll
            for (int j = 0; j < 25; j++)
                row[j] = alpha * (ebuf[j] * inv) + sm[OQR + i * 28 + j];
        } else {
#pragma unroll
            for (int j = 0; j < 25; j++)
                row[j] = beta * (ebuf[j] * inv);
        }
    }
    __syncthreads();

    if (tid < 80) {
        int ig = tid / 16;
        int dg = tid % 16;
        float aX[5][4], aE[5][4];
#pragma unroll
        for (int ii = 0; ii < 5; ii++)
#pragma unroll
            for (int dd = 0; dd < 4; dd++) { aX[ii][dd] = 0.f; aE[ii][dd] = 0.f; }
#pragma unroll
        for (int j = 0; j < 25; j++) {
            float4 v4 = *reinterpret_cast<const float4*>(&sm[OV + j * P + dg * 4]);
#pragma unroll
            for (int ii = 0; ii < 5; ii++) {
                float a  = sm[OS + (ig * 5 + ii) * 28 + j];
                float dc = sm[OD + (ig * 5 + ii) * 28 + j];
                aX[ii][0] += a * v4.x;  aX[ii][1] += a * v4.y;
                aX[ii][2] += a * v4.z;  aX[ii][3] += a * v4.w;
                aE[ii][0] += dc * v4.x; aE[ii][1] += dc * v4.y;
                aE[ii][2] += dc * v4.z; aE[ii][3] += dc * v4.w;
            }
        }
#pragma unroll
        for (int ii = 0; ii < 5; ii++) {
            int i = ig * 5 + ii;
#pragma unroll
            for (int dd = 0; dd < 4; dd++) {
                int d = dg * 4 + dd;
                eo_out[(((size_t)n * DIMC + h * HD + d) * TT + t) * VV + i] = aE[ii][dd];
                sm[OXO + i * P + d] = aX[ii][dd];
            }
        }
    }
    for (int l = tid; l < 4096; l += 128)
        sm[OW + l] = proj_w[(size_t)h * 4096 + l];
    __syncthreads();

    if (tid < 80) {
        int ig = tid / 16;
        int og = tid % 16;
        float acc[5][4];
#pragma unroll
        for (int ii = 0; ii < 5; ii++)
#pragma unroll
            for (int oo = 0; oo < 4; oo++) acc[ii][oo] = 0.f;
#pragma unroll
        for (int c = 0; c < 64; c += 4) {
            float4 w4[4];
#pragma unroll
            for (int oo = 0; oo < 4; oo++)
                w4[oo] = *reinterpret_cast<const float4*>(&sm[OW + (og * 4 + oo) * 64 + c]);
#pragma unroll
            for (int ii = 0; ii < 5; ii++) {
                float4 x4 = *reinterpret_cast<const float4*>(&sm[OXO + (ig * 5 + ii) * P + c]);
#pragma unroll
                for (int oo = 0; oo < 4; oo++)
                    acc[ii][oo] += x4.x * w4[oo].x + x4.y * w4[oo].y
                                 + x4.z * w4[oo].z + x4.w * w4[oo].w;
            }
        }
#pragma unroll
        for (int oo = 0; oo < 4; oo++) {
            int o = og * 4 + oo;
            float b = __ldg(proj_b + h * HD + o);
#pragma unroll
            for (int ii = 0; ii < 5; ii++) {
                int i = ig * 5 + ii;
                xo_out[(((size_t)n * DIMC + h * HD + o) * TT + t) * VV + i] = acc[ii][oo] + b;
            }
        }
    }
}

extern "C" void kernel_launch(void* const* d_in, const int* in_sizes, int n_in,
                              void* d_out, int out_size)
{
    const float* x      = (const float*)d_in[0];
    const float* e      = (const float*)d_in[1];
    const float* kv_w   = (const float*)d_in[2];
    const float* q_w    = (const float*)d_in[3];
    const float* e_kv_w = (const float*)d_in[4];
    const float* e_q_w  = (const float*)d_in[5];
    const float* rpe    = (const float*)d_in[6];
    const float* outerp = (const float*)d_in[7];
    const float* alpha  = (const float*)d_in[8];
    const float* beta   = (const float*)d_in[9];
    const float* proj_w = (const float*)d_in[10];
    const float* proj_b = (const float*)d_in[11];
    const int*   hops   = (const int*)d_in[12];

    int nh = in_sizes[6] / DIMC;

    float* xo = (float*)d_out;
    float* eo = xo + (size_t)NB * DIMC * TT * VV;

    cudaFuncSetAttribute(proj_mma, cudaFuncAttributeMaxDynamicSharedMemorySize, DYN_BYTES);
    proj_mma<<<dim3(13, 15, NB), 256, DYN_BYTES>>>(x, e, kv_w, q_w, e_kv_w, e_q_w);
    attn_kernel<<<dim3(HH, TT, NB), 128>>>(rpe, outerp, alpha, beta,
                                           proj_w, proj_b, hops, nh, xo, eo);
}

// round 8
// speedup vs baseline: 2.1728x; 1.0700x over previous
#include <cuda_runtime.h>
#include <cuda_bf16.h>
#include <math.h>
#include <stdint.h>

#define NB   64
#define TT   64
#define VV   25
#define DIMC 384
#define HH   6
#define HD   64
#define TV   1600                 // T*V
#define SL   39321600             // N*T*H*HD*V  (per-slot scratch size)
#define NSTRIDE 614400u           // T*H*HD*V    (per-n stride within a slot)
#define XPITCH 1664               // padded TV for cp.async (multiple of 128)

// Scratch: slots 0..4 = K, V, Q, EK, EQ, each [N,T,H,HD,V] fp32
__device__ float g_proj[5u * SL];
// Pre-split GEMM operands (bf16 hi/lo)
__device__ __nv_bfloat16 g_whi[1920 * 384];
__device__ __nv_bfloat16 g_wlo[1920 * 384];
__device__ __nv_bfloat16 g_xhi[2u * NB * DIMC * XPITCH];
__device__ __nv_bfloat16 g_xlo[2u * NB * DIMC * XPITCH];

// ---------------- helpers ----------------
__device__ __forceinline__ uint32_t smem_u32(const void* p) {
    uint32_t a;
    asm("{ .reg .u64 t; cvta.to.shared.u64 t, %1; cvt.u32.u64 %0, t; }"
        : "=r"(a) : "l"(p));
    return a;
}
__device__ __forceinline__ void split4(float4 v, uint2& h, uint2& l) {
    __nv_bfloat162 h0 = __floats2bfloat162_rn(v.x, v.y);
    __nv_bfloat162 h1 = __floats2bfloat162_rn(v.z, v.w);
    float2 f0 = __bfloat1622float2(h0);
    float2 f1 = __bfloat1622float2(h1);
    __nv_bfloat162 l0 = __floats2bfloat162_rn(v.x - f0.x, v.y - f0.y);
    __nv_bfloat162 l1 = __floats2bfloat162_rn(v.z - f1.x, v.w - f1.y);
    h = make_uint2(*(uint32_t*)&h0, *(uint32_t*)&h1);
    l = make_uint2(*(uint32_t*)&l0, *(uint32_t*)&l1);
}
__device__ __forceinline__ void ldsm4(uint32_t addr, uint32_t* r) {
    asm volatile("ldmatrix.sync.aligned.m8n8.x4.shared.b16 {%0,%1,%2,%3}, [%4];"
                 : "=r"(r[0]), "=r"(r[1]), "=r"(r[2]), "=r"(r[3]) : "r"(addr));
}
__device__ __forceinline__ void ldsm4t(uint32_t addr, uint32_t* r) {
    asm volatile("ldmatrix.sync.aligned.m8n8.x4.trans.shared.b16 {%0,%1,%2,%3}, [%4];"
                 : "=r"(r[0]), "=r"(r[1]), "=r"(r[2]), "=r"(r[3]) : "r"(addr));
}
__device__ __forceinline__ void mma_bf16(float* c, const uint32_t* a, const uint32_t* b) {
    asm volatile("mma.sync.aligned.m16n8k16.row.col.f32.bf16.bf16.f32 "
                 "{%0,%1,%2,%3}, {%4,%5,%6,%7}, {%8,%9}, {%0,%1,%2,%3};"
                 : "+f"(c[0]), "+f"(c[1]), "+f"(c[2]), "+f"(c[3])
                 : "r"(a[0]), "r"(a[1]), "r"(a[2]), "r"(a[3]), "r"(b[0]), "r"(b[1]));
}
__device__ __forceinline__ void cp16(uint32_t dst, const void* src) {
    asm volatile("cp.async.cg.shared.global [%0], [%1], 16;" :: "r"(dst), "l"(src));
}
__device__ __forceinline__ void cp_commit() {
    asm volatile("cp.async.commit_group;" ::: "memory");
}
template <int N>
__device__ __forceinline__ void cp_wait() {
    asm volatile("cp.async.wait_group %0;" :: "n"(N) : "memory");
}

// =====================================================================
// Pre-split kernels: fp32 -> bf16 hi/lo
// =====================================================================
__global__ __launch_bounds__(256) void presplit_w(
    const float* __restrict__ kv_w, const float* __restrict__ q_w,
    const float* __restrict__ e_kv_w, const float* __restrict__ e_q_w)
{
    int id = blockIdx.x * 256 + threadIdx.x;       // float4 id, < 184320
    if (id >= 1920 * 384 / 4) return;
    int idx4 = id * 4;
    int r = idx4 / 384, c = idx4 % 384;
    const float* src;
    if      (r < 768)  src = kv_w   + (size_t)r * 384 + c;
    else if (r < 1152) src = q_w    + (size_t)(r - 768) * 384 + c;
    else if (r < 1536) src = e_kv_w + (size_t)(r - 1152) * 384 + c;
    else               src = e_q_w  + (size_t)(r - 1536) * 384 + c;
    float4 v = *(const float4*)src;
    uint2 h, l; split4(v, h, l);
    *(uint2*)&g_whi[idx4] = h;
    *(uint2*)&g_wlo[idx4] = l;
}

__global__ __launch_bounds__(256) void presplit_x(
    const float* __restrict__ x, const float* __restrict__ e)
{
    const int k = blockIdx.x, n = blockIdx.y, path = blockIdx.z;
    const float* src = (path ? e : x) + ((size_t)n * DIMC + k) * TV;
    size_t dst = ((size_t)(path * NB + n) * DIMC + k) * XPITCH;
    for (int l4 = threadIdx.x; l4 < XPITCH / 4; l4 += 256) {
        int f = l4 * 4;
        float4 v = (f < TV) ? *(const float4*)(src + f) : make_float4(0.f, 0.f, 0.f, 0.f);
        uint2 h, l; split4(v, h, l);
        *(uint2*)&g_xhi[dst + f] = h;
        *(uint2*)&g_xlo[dst + f] = l;
    }
}

// =====================================================================
// Projection GEMM via mma.sync bf16 (Markidis 3-split, fp32-grade).
// CTA tile: M=128 x N=128, K=384, BK=32, 3-stage cp.async pipeline.
// grid: x = 13 n-tiles, y = 15 m-tiles, z = 64 batch.
// =====================================================================
#define A_PITCH 80              // bytes per m-row (32 bf16 + pad), 5*16
#define B_PITCH 272             // bytes per k-row (128 bf16 + pad), 17*16
#define A_BYTES (128 * A_PITCH) // 10240
#define B_BYTES (32 * B_PITCH)  // 8704
#define STAGE_BYTES (2 * A_BYTES + 2 * B_BYTES)  // 37888
#define DYN_BYTES (3 * STAGE_BYTES)              // 113664

__global__ __launch_bounds__(256, 2)
void proj_mma()
{
    const int nt  = blockIdx.x;     // 0..12
    const int mt  = blockIdx.y;     // 0..14
    const int n   = blockIdx.z;     // 0..63
    const int tid = threadIdx.x;
    const int lane = tid & 31;
    const int w    = tid >> 5;
    const int wm   = w & 3;         // m-warp 0..3 (rows wm*32)
    const int wn   = w >> 2;        // n-warp 0..1 (cols wn*64)

    extern __shared__ char smem[];
    const uint32_t smem_b = smem_u32(smem);

    const int path = (mt >= 9);
    const int o_origin = (mt < 12) ? ((mt < 9) ? mt * 128 : (mt - 9) * 128)
                                   : (384 + (mt - 12) * 128);
    const int wrow0 = mt * 128;
    const int p0 = nt * 128;

    const __nv_bfloat16* Xhi = g_xhi + ((size_t)(path * NB + n) * DIMC) * XPITCH;
    const __nv_bfloat16* Xlo = g_xlo + ((size_t)(path * NB + n) * DIMC) * XPITCH;

    // ---- cp.async per-thread segment indices ----
    // A: 512 16B segs (128 rows x 4), thread handles segs tid*2, tid*2+1 per array
    const int a_row0 = (tid * 2) >> 2;         // row of first seg
    const int a_s0   = (tid * 2) & 3;          // seg-in-row of first seg
    // B: 512 16B segs (32 rows x 16), thread handles segs tid*2, tid*2+1
    const int b_row0 = (tid * 2) >> 4;
    const int b_s0   = (tid * 2) & 15;

    // ---- ldmatrix per-lane addresses (byte offsets within stage) ----
    const uint32_t aoff = (uint32_t)((wm * 32 + (lane & 15)) * A_PITCH + (lane >> 4) * 16);
    const uint32_t boff = (uint32_t)((lane & 15) * B_PITCH + (wn * 64 + (lane >> 4) * 8) * 2);

    float acc[16][4];
#pragma unroll
    for (int i = 0; i < 16; i++)
#pragma unroll
        for (int j = 0; j < 4; j++) acc[i][j] = 0.f;

    // ---- issue chunk c into stage c%3 ----
    auto issue = [&](int c) {
        const int k0 = c * 32;
        const uint32_t st = smem_b + (uint32_t)((c % 3) * STAGE_BYTES);
#pragma unroll
        for (int i = 0; i < 2; i++) {
            int ar = a_row0 + ((a_s0 + i) >> 2 == 1 ? 1 : 0);  // careful: segs consecutive
            int as = (a_s0 + i) & 3;
            if (a_s0 + i >= 4) { ar = a_row0 + 1; }
            size_t asrc = (size_t)(wrow0 + ar) * 384 + k0 + as * 8;
            uint32_t adst = st + (uint32_t)(ar * A_PITCH + as * 16);
            cp16(adst, g_whi + asrc);
            cp16(adst + A_BYTES, g_wlo + asrc);
            int br = b_row0 + ((b_s0 + i) >= 16 ? 1 : 0);
            int bs = (b_s0 + i) & 15;
            size_t bsrc = (size_t)(k0 + br) * XPITCH + p0 + bs * 8;
            uint32_t bdst = st + (uint32_t)(2 * A_BYTES + br * B_PITCH + bs * 16);
            cp16(bdst, Xhi + bsrc);
            cp16(bdst + B_BYTES, Xlo + bsrc);
        }
        cp_commit();
    };

    issue(0);
    issue(1);

    for (int c = 0; c < 12; ++c) {
        if (c < 11) cp_wait<1>(); else cp_wait<0>();
        __syncthreads();
        if (c < 10) issue(c + 2);

        const uint32_t stage = smem_b + (uint32_t)((c % 3) * STAGE_BYTES);
        const uint32_t aHi = stage + aoff;
        const uint32_t aLo = aHi + A_BYTES;
        const uint32_t bHi = stage + 2 * A_BYTES + boff;
        const uint32_t bLo = bHi + B_BYTES;
#pragma unroll
        for (int s = 0; s < 2; s++) {
            uint32_t Ah[2][4], Al[2][4];
#pragma unroll
            for (int m = 0; m < 2; m++) {
                ldsm4(aHi + m * 16 * A_PITCH + s * 32, Ah[m]);
                ldsm4(aLo + m * 16 * A_PITCH + s * 32, Al[m]);
            }
            uint32_t Bh[4][4], Bl[4][4];
#pragma unroll
            for (int g = 0; g < 4; g++) {
                ldsm4t(bHi + s * 16 * B_PITCH + g * 32, Bh[g]);
                ldsm4t(bLo + s * 16 * B_PITCH + g * 32, Bl[g]);
            }
#pragma unroll
            for (int m = 0; m < 2; m++)
#pragma unroll
                for (int g = 0; g < 4; g++)
#pragma unroll
                    for (int half = 0; half < 2; half++) {
                        float* cc = acc[m * 8 + g * 2 + half];
                        mma_bf16(cc, Ah[m], &Bh[g][half * 2]);
                        mma_bf16(cc, Ah[m], &Bl[g][half * 2]);
                        mma_bf16(cc, Al[m], &Bh[g][half * 2]);
                    }
        }
        __syncthreads();
    }

    // ---- epilogue: scatter C to g_proj ----
    const int g   = lane >> 2;
    const int tig = lane & 3;
#pragma unroll
    for (int m = 0; m < 2; m++) {
#pragma unroll
        for (int ntile = 0; ntile < 8; ntile++) {
#pragma unroll
            for (int j = 0; j < 4; j++) {
                int o_g = o_origin + wm * 32 + m * 16 + g + (j >> 1) * 8;
                uint32_t p = (uint32_t)(p0 + wn * 64 + ntile * 8 + tig * 2 + (j & 1));
                if (p < TV) {
                    int cdiv = o_g / 384;
                    int slot = cdiv + (path ? 3 : 0);
                    int rem  = o_g - cdiv * 384;
                    int hh = rem >> 6, dd = rem & 63;
                    uint32_t t = (p * 5243u) >> 17;
                    uint32_t v = p - t * 25u;
                    uint32_t addr = (uint32_t)slot * (uint32_t)SL + (uint32_t)n * NSTRIDE
                                  + t * 9600u + (uint32_t)hh * 1600u + (uint32_t)dd * 25u + v;
                    g_proj[addr] = acc[m * 8 + ntile][j];
                }
            }
        }
    }
}

// =====================================================================
// Kernel B: attention + fused grouped projection. One block per (n,t,h).
// =====================================================================
__global__ __launch_bounds__(128) void attn_kernel(
    const float* __restrict__ rpe, const float* __restrict__ outer,
    const float* __restrict__ alpha_p, const float* __restrict__ beta_p,
    const float* __restrict__ proj_w, const float* __restrict__ proj_b,
    const int* __restrict__ hops, int nh,
    float* __restrict__ xo_out, float* __restrict__ eo_out)
{
    const int h = blockIdx.x, t = blockIdx.y, n = blockIdx.z;
    const int tid = threadIdx.x;

    __shared__ float sm[10600];
    __shared__ unsigned char shops[640];

    const int P = 68;
    const int OQ = 0, OEQ = 1700, OEK = 3400, OKE = 5100, OV = 6800;
    const int OS = 8500, OD = 9200, OQR = 9900;
    const int OXO = OKE;
    const int OW  = 0;

    const size_t base = (((size_t)n * TT + t) * HH + h) * (size_t)(HD * VV);

    // ---- load tiles via float4 over flat [d][v] (base is 16B aligned) ----
    for (int l4 = tid; l4 < 400; l4 += 128) {
        int f = l4 * 4;
        float4 k4 = *(const float4*)&g_proj[0 * (size_t)SL + base + f];
        float4 v4 = *(const float4*)&g_proj[1 * (size_t)SL + base + f];
        float4 q4 = *(const float4*)&g_proj[2 * (size_t)SL + base + f];
        float4 ek4 = *(const float4*)&g_proj[3 * (size_t)SL + base + f];
        float4 eq4 = *(const float4*)&g_proj[4 * (size_t)SL + base + f];
        float kk[4] = {k4.x, k4.y, k4.z, k4.w};
        float vv[4] = {v4.x, v4.y, v4.z, v4.w};
        float qq[4] = {q4.x, q4.y, q4.z, q4.w};
        float ek[4] = {ek4.x, ek4.y, ek4.z, ek4.w};
        float eq[4] = {eq4.x, eq4.y, eq4.z, eq4.w};
#pragma unroll
        for (int e2 = 0; e2 < 4; e2++) {
            uint32_t fe = (uint32_t)(f + e2);
            uint32_t d = (fe * 5243u) >> 17;
            uint32_t v = fe - d * 25u;
            sm[OQ  + v * P + d] = qq[e2];
            sm[OEQ + v * P + d] = eq[e2];
            sm[OEK + v * P + d] = ek[e2];
            sm[OKE + v * P + d] = kk[e2] + ek[e2];
            sm[OV  + v * P + d] = vv[e2];
        }
    }
    for (int l = tid; l < 625; l += 128) shops[l] = (unsigned char)hops[l];
    __syncthreads();

    for (int l = tid; l < 25 * nh; l += 128) {
        int i = l / nh, hp = l % nh;
        const float* rr = rpe + (size_t)hp * DIMC + h * HD;
        const float* qi = &sm[OQ + i * P];
        float acc = 0.f;
#pragma unroll
        for (int d = 0; d < 64; d += 4) {
            float4 q4 = *reinterpret_cast<const float4*>(qi + d);
            float4 r4 = *reinterpret_cast<const float4*>(rr + d);
            acc += q4.x * r4.x + q4.y * r4.y + q4.z * r4.z + q4.w * r4.w;
        }
        sm[OQR + i * 28 + hp] = acc;
    }
    __syncthreads();

    if (tid < 125) {
        int i = tid / 5, jg = tid % 5;
        float s1[5] = {0, 0, 0, 0, 0};
        float s2[5] = {0, 0, 0, 0, 0};
        const float* qi  = &sm[OQ  + i * P];
        const float* eqi = &sm[OEQ + i * P];
#pragma unroll
        for (int d = 0; d < 64; d += 4) {
            float4 q4 = *reinterpret_cast<const float4*>(qi + d);
            float4 e4 = *reinterpret_cast<const float4*>(eqi + d);
#pragma unroll
            for (int jj = 0; jj < 5; jj++) {
                int j = jg * 5 + jj;
                float4 k4 = *reinterpret_cast<const float4*>(&sm[OKE + j * P + d]);
                float4 x4 = *reinterpret_cast<const float4*>(&sm[OEK + j * P + d]);
                s1[jj] += q4.x * k4.x + q4.y * k4.y + q4.z * k4.z + q4.w * k4.w;
                s2[jj] += e4.x * x4.x + e4.y * x4.y + e4.z * x4.z + e4.w * x4.w;
            }
        }
#pragma unroll
        for (int jj = 0; jj < 5; jj++) {
            int j = jg * 5 + jj;
            float b = sm[OQR + i * 28 + shops[i * 25 + j]];
            sm[OS + i * 28 + j] = s1[jj] + s2[jj] + b;
            sm[OD + i * 28 + j] = s2[jj];
        }
    }
    __syncthreads();

    for (int l = tid; l < 625; l += 128)
        sm[OQR + (l / 25) * 28 + (l % 25)] = outer[(size_t)h * 625 + l];
    __syncthreads();

    const float alpha = __ldg(alpha_p);
    const float beta  = __ldg(beta_p);
    const float scale = 0.125f;

    if (tid < 50) {
        int i = tid % 25;
        float* row = &sm[(tid < 25 ? OS : OD) + i * 28];
        float m = -1e30f;
#pragma unroll
        for (int j = 0; j < 25; j++) m = fmaxf(m, row[j]);
        float ebuf[25];
        float s = 0.f;
#pragma unroll
        for (int j = 0; j < 25; j++) { float v = expf((row[j] - m) * scale); ebuf[j] = v; s += v; }
        float inv = 1.f / s;
        if (tid < 25) {
#pragma unroll
            for (int j = 0; j < 25; j++)
                row[j] = alpha * (ebuf[j] * inv) + sm[OQR + i * 28 + j];
        } else {
#pragma unroll
            for (int j = 0; j < 25; j++)
                row[j] = beta * (ebuf[j] * inv);
        }
    }
    __syncthreads();

    if (tid < 80) {
        int ig = tid / 16;
        int dg = tid % 16;
        float aX[5][4], aE[5][4];
#pragma unroll
        for (int ii = 0; ii < 5; ii++)
#pragma unroll
            for (int dd = 0; dd < 4; dd++) { aX[ii][dd] = 0.f; aE[ii][dd] = 0.f; }
#pragma unroll
        for (int j = 0; j < 25; j++) {
            float4 v4 = *reinterpret_cast<const float4*>(&sm[OV + j * P + dg * 4]);
#pragma unroll
            for (int ii = 0; ii < 5; ii++) {
                float a  = sm[OS + (ig * 5 + ii) * 28 + j];
                float dc = sm[OD + (ig * 5 + ii) * 28 + j];
                aX[ii][0] += a * v4.x;  aX[ii][1] += a * v4.y;
                aX[ii][2] += a * v4.z;  aX[ii][3] += a * v4.w;
                aE[ii][0] += dc * v4.x; aE[ii][1] += dc * v4.y;
                aE[ii][2] += dc * v4.z; aE[ii][3] += dc * v4.w;
            }
        }
#pragma unroll
        for (int ii = 0; ii < 5; ii++) {
            int i = ig * 5 + ii;
#pragma unroll
            for (int dd = 0; dd < 4; dd++) {
                int d = dg * 4 + dd;
                eo_out[(((size_t)n * DIMC + h * HD + d) * TT + t) * VV + i] = aE[ii][dd];
                sm[OXO + i * P + d] = aX[ii][dd];
            }
        }
    }
    for (int l = tid; l < 4096; l += 128)
        sm[OW + l] = proj_w[(size_t)h * 4096 + l];
    __syncthreads();

    if (tid < 80) {
        int ig = tid / 16;
        int og = tid % 16;
        float acc[5][4];
#pragma unroll
        for (int ii = 0; ii < 5; ii++)
#pragma unroll
            for (int oo = 0; oo < 4; oo++) acc[ii][oo] = 0.f;
#pragma unroll
        for (int c = 0; c < 64; c += 4) {
            float4 w4[4];
#pragma unroll
            for (int oo = 0; oo < 4; oo++)
                w4[oo] = *reinterpret_cast<const float4*>(&sm[OW + (og * 4 + oo) * 64 + c]);
#pragma unroll
            for (int ii = 0; ii < 5; ii++) {
                float4 x4 = *reinterpret_cast<const float4*>(&sm[OXO + (ig * 5 + ii) * P + c]);
#pragma unroll
                for (int oo = 0; oo < 4; oo++)
                    acc[ii][oo] += x4.x * w4[oo].x + x4.y * w4[oo].y
                                 + x4.z * w4[oo].z + x4.w * w4[oo].w;
            }
        }
#pragma unroll
        for (int oo = 0; oo < 4; oo++) {
            int o = og * 4 + oo;
            float b = __ldg(proj_b + h * HD + o);
#pragma unroll
            for (int ii = 0; ii < 5; ii++) {
                int i = ig * 5 + ii;
                xo_out[(((size_t)n * DIMC + h * HD + o) * TT + t) * VV + i] = acc[ii][oo] + b;
            }
        }
    }
}

extern "C" void kernel_launch(void* const* d_in, const int* in_sizes, int n_in,
                              void* d_out, int out_size)
{
    const float* x      = (const float*)d_in[0];
    const float* e      = (const float*)d_in[1];
    const float* kv_w   = (const float*)d_in[2];
    const float* q_w    = (const float*)d_in[3];
    const float* e_kv_w = (const float*)d_in[4];
    const float* e_q_w  = (const float*)d_in[5];
    const float* rpe    = (const float*)d_in[6];
    const float* outerp = (const float*)d_in[7];
    const float* alpha  = (const float*)d_in[8];
    const float* beta   = (const float*)d_in[9];
    const float* proj_w = (const float*)d_in[10];
    const float* proj_b = (const float*)d_in[11];
    const int*   hops   = (const int*)d_in[12];

    int nh = in_sizes[6] / DIMC;

    float* xo = (float*)d_out;
    float* eo = xo + (size_t)NB * DIMC * TT * VV;

    presplit_w<<<(1920 * 384 / 4 + 255) / 256, 256>>>(kv_w, q_w, e_kv_w, e_q_w);
    presplit_x<<<dim3(DIMC, NB, 2), 256>>>(x, e);

    cudaFuncSetAttribute(proj_mma, cudaFuncAttributeMaxDynamicSharedMemorySize, DYN_BYTES);
    proj_mma<<<dim3(13, 15, NB), 256, DYN_BYTES>>>();
    attn_kernel<<<dim3(HH, TT, NB), 128>>>(rpe, outerp, alpha, beta,
                                           proj_w, proj_b, hops, nh, xo, eo);
}

// round 9
// speedup vs baseline: 2.2738x; 1.0465x over previous
#include <cuda_runtime.h>
#include <cuda_bf16.h>
#include <math.h>
#include <stdint.h>

#define NB   64
#define TT   64
#define VV   25
#define DIMC 384
#define HH   6
#define HD   64
#define TV   1600                 // T*V
#define SL   39321600             // N*T*H*HD*V  (per-slot scratch size)
#define NSTRIDE 614400u           // T*H*HD*V    (per-n stride within a slot)
#define XPITCH 1664               // padded TV for cp.async (multiple of 128)

// Scratch: slots 0..4 = K, V, Q, EK, EQ, each [N,T,H,V,HD] fp32 (v-major inner!)
__device__ float g_proj[5u * SL];
// Pre-split GEMM operands (bf16 hi/lo)
__device__ __nv_bfloat16 g_whi[1920 * 384];
__device__ __nv_bfloat16 g_wlo[1920 * 384];
__device__ __nv_bfloat16 g_xhi[2u * NB * DIMC * XPITCH];
__device__ __nv_bfloat16 g_xlo[2u * NB * DIMC * XPITCH];

// ---------------- helpers ----------------
__device__ __forceinline__ uint32_t smem_u32(const void* p) {
    uint32_t a;
    asm("{ .reg .u64 t; cvta.to.shared.u64 t, %1; cvt.u32.u64 %0, t; }"
        : "=r"(a) : "l"(p));
    return a;
}
__device__ __forceinline__ void split4(float4 v, uint2& h, uint2& l) {
    __nv_bfloat162 h0 = __floats2bfloat162_rn(v.x, v.y);
    __nv_bfloat162 h1 = __floats2bfloat162_rn(v.z, v.w);
    float2 f0 = __bfloat1622float2(h0);
    float2 f1 = __bfloat1622float2(h1);
    __nv_bfloat162 l0 = __floats2bfloat162_rn(v.x - f0.x, v.y - f0.y);
    __nv_bfloat162 l1 = __floats2bfloat162_rn(v.z - f1.x, v.w - f1.y);
    h = make_uint2(*(uint32_t*)&h0, *(uint32_t*)&h1);
    l = make_uint2(*(uint32_t*)&l0, *(uint32_t*)&l1);
}
__device__ __forceinline__ void ldsm4(uint32_t addr, uint32_t* r) {
    asm volatile("ldmatrix.sync.aligned.m8n8.x4.shared.b16 {%0,%1,%2,%3}, [%4];"
                 : "=r"(r[0]), "=r"(r[1]), "=r"(r[2]), "=r"(r[3]) : "r"(addr));
}
__device__ __forceinline__ void ldsm4t(uint32_t addr, uint32_t* r) {
    asm volatile("ldmatrix.sync.aligned.m8n8.x4.trans.shared.b16 {%0,%1,%2,%3}, [%4];"
                 : "=r"(r[0]), "=r"(r[1]), "=r"(r[2]), "=r"(r[3]) : "r"(addr));
}
__device__ __forceinline__ void mma_bf16(float* c, const uint32_t* a, const uint32_t* b) {
    asm volatile("mma.sync.aligned.m16n8k16.row.col.f32.bf16.bf16.f32 "
                 "{%0,%1,%2,%3}, {%4,%5,%6,%7}, {%8,%9}, {%0,%1,%2,%3};"
                 : "+f"(c[0]), "+f"(c[1]), "+f"(c[2]), "+f"(c[3])
                 : "r"(a[0]), "r"(a[1]), "r"(a[2]), "r"(a[3]), "r"(b[0]), "r"(b[1]));
}
__device__ __forceinline__ void cp16(uint32_t dst, const void* src) {
    asm volatile("cp.async.cg.shared.global [%0], [%1], 16;" :: "r"(dst), "l"(src));
}
__device__ __forceinline__ void cp_commit() {
    asm volatile("cp.async.commit_group;" ::: "memory");
}
template <int N>
__device__ __forceinline__ void cp_wait() {
    asm volatile("cp.async.wait_group %0;" :: "n"(N) : "memory");
}

// =====================================================================
// Pre-split kernels: fp32 -> bf16 hi/lo
// =====================================================================
__global__ __launch_bounds__(256) void presplit_w(
    const float* __restrict__ kv_w, const float* __restrict__ q_w,
    const float* __restrict__ e_kv_w, const float* __restrict__ e_q_w)
{
    int id = blockIdx.x * 256 + threadIdx.x;       // float4 id, < 184320
    if (id >= 1920 * 384 / 4) return;
    int idx4 = id * 4;
    int r = idx4 / 384, c = idx4 % 384;
    const float* src;
    if      (r < 768)  src = kv_w   + (size_t)r * 384 + c;
    else if (r < 1152) src = q_w    + (size_t)(r - 768) * 384 + c;
    else if (r < 1536) src = e_kv_w + (size_t)(r - 1152) * 384 + c;
    else               src = e_q_w  + (size_t)(r - 1536) * 384 + c;
    float4 v = *(const float4*)src;
    uint2 h, l; split4(v, h, l);
    *(uint2*)&g_whi[idx4] = h;
    *(uint2*)&g_wlo[idx4] = l;
}

__global__ __launch_bounds__(256) void presplit_x(
    const float* __restrict__ x, const float* __restrict__ e)
{
    const int k = blockIdx.x, n = blockIdx.y, path = blockIdx.z;
    const float* src = (path ? e : x) + ((size_t)n * DIMC + k) * TV;
    size_t dst = ((size_t)(path * NB + n) * DIMC + k) * XPITCH;
    for (int l4 = threadIdx.x; l4 < XPITCH / 4; l4 += 256) {
        int f = l4 * 4;
        float4 v = (f < TV) ? *(const float4*)(src + f) : make_float4(0.f, 0.f, 0.f, 0.f);
        uint2 h, l; split4(v, h, l);
        *(uint2*)&g_xhi[dst + f] = h;
        *(uint2*)&g_xlo[dst + f] = l;
    }
}

// =====================================================================
// Projection GEMM via mma.sync bf16 (Markidis 3-split, fp32-grade).
// CTA tile: M=128 x N=128, K=384, BK=32, 3-stage cp.async pipeline.
// grid: x = 13 n-tiles, y = 15 m-tiles, z = 64 batch.
// =====================================================================
#define A_PITCH 80              // bytes per m-row (32 bf16 + pad), 5*16
#define B_PITCH 272             // bytes per k-row (128 bf16 + pad), 17*16
#define A_BYTES (128 * A_PITCH) // 10240
#define B_BYTES (32 * B_PITCH)  // 8704
#define STAGE_BYTES (2 * A_BYTES + 2 * B_BYTES)  // 37888
#define DYN_BYTES (3 * STAGE_BYTES)              // 113664

__global__ __launch_bounds__(256, 2)
void proj_mma()
{
    const int nt  = blockIdx.x;     // 0..12
    const int mt  = blockIdx.y;     // 0..14
    const int n   = blockIdx.z;     // 0..63
    const int tid = threadIdx.x;
    const int lane = tid & 31;
    const int w    = tid >> 5;
    const int wm   = w & 3;         // m-warp 0..3 (rows wm*32)
    const int wn   = w >> 2;        // n-warp 0..1 (cols wn*64)

    extern __shared__ char smem[];
    const uint32_t smem_b = smem_u32(smem);

    const int path = (mt >= 9);
    const int o_origin = (mt < 12) ? ((mt < 9) ? mt * 128 : (mt - 9) * 128)
                                   : (384 + (mt - 12) * 128);
    const int wrow0 = mt * 128;
    const int p0 = nt * 128;

    const __nv_bfloat16* Xhi = g_xhi + ((size_t)(path * NB + n) * DIMC) * XPITCH;
    const __nv_bfloat16* Xlo = g_xlo + ((size_t)(path * NB + n) * DIMC) * XPITCH;

    // ---- cp.async per-thread segment indices ----
    const int a_row0 = (tid * 2) >> 2;
    const int a_s0   = (tid * 2) & 3;
    const int b_row0 = (tid * 2) >> 4;
    const int b_s0   = (tid * 2) & 15;

    // ---- ldmatrix per-lane addresses (byte offsets within stage) ----
    const uint32_t aoff = (uint32_t)((wm * 32 + (lane & 15)) * A_PITCH + (lane >> 4) * 16);
    const uint32_t boff = (uint32_t)((lane & 15) * B_PITCH + (wn * 64 + (lane >> 4) * 8) * 2);

    float acc[16][4];
#pragma unroll
    for (int i = 0; i < 16; i++)
#pragma unroll
        for (int j = 0; j < 4; j++) acc[i][j] = 0.f;

    auto issue = [&](int c) {
        const int k0 = c * 32;
        const uint32_t st = smem_b + (uint32_t)((c % 3) * STAGE_BYTES);
#pragma unroll
        for (int i = 0; i < 2; i++) {
            int ar = a_row0;
            int as = (a_s0 + i) & 3;
            if (a_s0 + i >= 4) { ar = a_row0 + 1; }
            size_t asrc = (size_t)(wrow0 + ar) * 384 + k0 + as * 8;
            uint32_t adst = st + (uint32_t)(ar * A_PITCH + as * 16);
            cp16(adst, g_whi + asrc);
            cp16(adst + A_BYTES, g_wlo + asrc);
            int br = b_row0 + ((b_s0 + i) >= 16 ? 1 : 0);
            int bs = (b_s0 + i) & 15;
            size_t bsrc = (size_t)(k0 + br) * XPITCH + p0 + bs * 8;
            uint32_t bdst = st + (uint32_t)(2 * A_BYTES + br * B_PITCH + bs * 16);
            cp16(bdst, Xhi + bsrc);
            cp16(bdst + B_BYTES, Xlo + bsrc);
        }
        cp_commit();
    };

    issue(0);
    issue(1);

    for (int c = 0; c < 12; ++c) {
        if (c < 11) cp_wait<1>(); else cp_wait<0>();
        __syncthreads();
        if (c < 10) issue(c + 2);

        const uint32_t stage = smem_b + (uint32_t)((c % 3) * STAGE_BYTES);
        const uint32_t aHi = stage + aoff;
        const uint32_t aLo = aHi + A_BYTES;
        const uint32_t bHi = stage + 2 * A_BYTES + boff;
        const uint32_t bLo = bHi + B_BYTES;
#pragma unroll
        for (int s = 0; s < 2; s++) {
            uint32_t Ah[2][4], Al[2][4];
#pragma unroll
            for (int m = 0; m < 2; m++) {
                ldsm4(aHi + m * 16 * A_PITCH + s * 32, Ah[m]);
                ldsm4(aLo + m * 16 * A_PITCH + s * 32, Al[m]);
            }
            uint32_t Bh[4][4], Bl[4][4];
#pragma unroll
            for (int g = 0; g < 4; g++) {
                ldsm4t(bHi + s * 16 * B_PITCH + g * 32, Bh[g]);
                ldsm4t(bLo + s * 16 * B_PITCH + g * 32, Bl[g]);
            }
#pragma unroll
            for (int m = 0; m < 2; m++)
#pragma unroll
                for (int g = 0; g < 4; g++)
#pragma unroll
                    for (int half = 0; half < 2; half++) {
                        float* cc = acc[m * 8 + g * 2 + half];
                        mma_bf16(cc, Ah[m], &Bh[g][half * 2]);
                        mma_bf16(cc, Ah[m], &Bl[g][half * 2]);
                        mma_bf16(cc, Al[m], &Bh[g][half * 2]);
                    }
        }
        __syncthreads();
    }

    // ---- epilogue: scatter C to g_proj ([N,T,H,V,HD] layout) ----
    const int g   = lane >> 2;
    const int tig = lane & 3;
#pragma unroll
    for (int m = 0; m < 2; m++) {
#pragma unroll
        for (int ntile = 0; ntile < 8; ntile++) {
#pragma unroll
            for (int j = 0; j < 4; j++) {
                int o_g = o_origin + wm * 32 + m * 16 + g + (j >> 1) * 8;
                uint32_t p = (uint32_t)(p0 + wn * 64 + ntile * 8 + tig * 2 + (j & 1));
                if (p < TV) {
                    int cdiv = o_g / 384;
                    int slot = cdiv + (path ? 3 : 0);
                    int rem  = o_g - cdiv * 384;
                    int hh = rem >> 6, dd = rem & 63;
                    uint32_t t = (p * 5243u) >> 17;
                    uint32_t v = p - t * 25u;
                    uint32_t addr = (uint32_t)slot * (uint32_t)SL + (uint32_t)n * NSTRIDE
                                  + t * 9600u + (uint32_t)hh * 1600u + v * 64u + (uint32_t)dd;
                    g_proj[addr] = acc[m * 8 + ntile][j];
                }
            }
        }
    }
}

// =====================================================================
// Kernel B: attention + fused grouped projection. One block per (n,t,h).
// =====================================================================
__global__ __launch_bounds__(128) void attn_kernel(
    const float* __restrict__ rpe, const float* __restrict__ outer,
    const float* __restrict__ alpha_p, const float* __restrict__ beta_p,
    const float* __restrict__ proj_w, const float* __restrict__ proj_b,
    const int* __restrict__ hops, int nh,
    float* __restrict__ xo_out, float* __restrict__ eo_out)
{
    const int h = blockIdx.x, t = blockIdx.y, n = blockIdx.z;
    const int tid = threadIdx.x;

    __shared__ float sm[10600];
    __shared__ unsigned char shops[640];

    const int P = 68;
    const int OQ = 0, OEQ = 1700, OEK = 3400, OKE = 5100, OV = 6800;
    const int OS = 8500, OD = 9200, OQR = 9900;
    const int OXO = OKE;
    const int OW  = 0;

    const size_t base = (((size_t)n * TT + t) * HH + h) * (size_t)(HD * VV);

    // ---- load tiles: gmem is [v][d] now; straight float4 copy, STS.128 ----
    for (int l4 = tid; l4 < 400; l4 += 128) {
        int f = l4 * 4;
        int v = f >> 6, d = f & 63;
        float4 k4  = *(const float4*)&g_proj[0 * (size_t)SL + base + f];
        float4 v4  = *(const float4*)&g_proj[1 * (size_t)SL + base + f];
        float4 q4  = *(const float4*)&g_proj[2 * (size_t)SL + base + f];
        float4 ek4 = *(const float4*)&g_proj[3 * (size_t)SL + base + f];
        float4 eq4 = *(const float4*)&g_proj[4 * (size_t)SL + base + f];
        float4 ke4 = make_float4(k4.x + ek4.x, k4.y + ek4.y, k4.z + ek4.z, k4.w + ek4.w);
        int o = v * P + d;
        *(float4*)&sm[OQ  + o] = q4;
        *(float4*)&sm[OEQ + o] = eq4;
        *(float4*)&sm[OEK + o] = ek4;
        *(float4*)&sm[OKE + o] = ke4;
        *(float4*)&sm[OV  + o] = v4;
    }
    for (int l = tid; l < 625; l += 128) shops[l] = (unsigned char)hops[l];
    __syncthreads();

    // ---- qR[i][hop] = q_i · rpe[hop, h*64:...] ----
    for (int l = tid; l < 25 * nh; l += 128) {
        int i = l / nh, hp = l % nh;
        const float* rr = rpe + (size_t)hp * DIMC + h * HD;
        const float* qi = &sm[OQ + i * P];
        float acc = 0.f;
#pragma unroll
        for (int d = 0; d < 64; d += 4) {
            float4 q4 = *reinterpret_cast<const float4*>(qi + d);
            float4 r4 = *reinterpret_cast<const float4*>(rr + d);
            acc += q4.x * r4.x + q4.y * r4.y + q4.z * r4.z + q4.w * r4.w;
        }
        sm[OQR + i * 28 + hp] = acc;
    }
    __syncthreads();

    // ---- scores ----
    if (tid < 125) {
        int i = tid / 5, jg = tid % 5;
        float s1[5] = {0, 0, 0, 0, 0};
        float s2[5] = {0, 0, 0, 0, 0};
        const float* qi  = &sm[OQ  + i * P];
        const float* eqi = &sm[OEQ + i * P];
#pragma unroll
        for (int d = 0; d < 64; d += 4) {
            float4 q4 = *reinterpret_cast<const float4*>(qi + d);
            float4 e4 = *reinterpret_cast<const float4*>(eqi + d);
#pragma unroll
            for (int jj = 0; jj < 5; jj++) {
                int j = jg * 5 + jj;
                float4 k4 = *reinterpret_cast<const float4*>(&sm[OKE + j * P + d]);
                float4 x4 = *reinterpret_cast<const float4*>(&sm[OEK + j * P + d]);
                s1[jj] += q4.x * k4.x + q4.y * k4.y + q4.z * k4.z + q4.w * k4.w;
                s2[jj] += e4.x * x4.x + e4.y * x4.y + e4.z * x4.z + e4.w * x4.w;
            }
        }
#pragma unroll
        for (int jj = 0; jj < 5; jj++) {
            int j = jg * 5 + jj;
            float b = sm[OQR + i * 28 + shops[i * 25 + j]];
            sm[OS + i * 28 + j] = s1[jj] + s2[jj] + b;
            sm[OD + i * 28 + j] = s2[jj];
        }
    }
    __syncthreads();

    const float alpha = __ldg(alpha_p);
    const float beta  = __ldg(beta_p);
    const float scale = 0.125f;

    // ---- softmax (50 rows), fold alpha/outer/beta; outer straight from L2 ----
    if (tid < 50) {
        int i = tid % 25;
        float* row = &sm[(tid < 25 ? OS : OD) + i * 28];
        float m = -1e30f;
#pragma unroll
        for (int j = 0; j < 25; j++) m = fmaxf(m, row[j]);
        float ebuf[25];
        float s = 0.f;
#pragma unroll
        for (int j = 0; j < 25; j++) { float v = expf((row[j] - m) * scale); ebuf[j] = v; s += v; }
        float inv = 1.f / s;
        if (tid < 25) {
            const float* orow = outer + (size_t)h * 625 + i * 25;
#pragma unroll
            for (int j = 0; j < 25; j++)
                row[j] = alpha * (ebuf[j] * inv) + __ldg(orow + j);
        } else {
#pragma unroll
            for (int j = 0; j < 25; j++)
                row[j] = beta * (ebuf[j] * inv);
        }
    }
    __syncthreads();

    // ---- AV for xo (to smem) and eo (to gmem) ----
    if (tid < 80) {
        int ig = tid / 16;
        int dg = tid % 16;
        float aX[5][4], aE[5][4];
#pragma unroll
        for (int ii = 0; ii < 5; ii++)
#pragma unroll
            for (int dd = 0; dd < 4; dd++) { aX[ii][dd] = 0.f; aE[ii][dd] = 0.f; }
#pragma unroll
        for (int j = 0; j < 25; j++) {
            float4 v4 = *reinterpret_cast<const float4*>(&sm[OV + j * P + dg * 4]);
#pragma unroll
            for (int ii = 0; ii < 5; ii++) {
                float a  = sm[OS + (ig * 5 + ii) * 28 + j];
                float dc = sm[OD + (ig * 5 + ii) * 28 + j];
                aX[ii][0] += a * v4.x;  aX[ii][1] += a * v4.y;
                aX[ii][2] += a * v4.z;  aX[ii][3] += a * v4.w;
                aE[ii][0] += dc * v4.x; aE[ii][1] += dc * v4.y;
                aE[ii][2] += dc * v4.z; aE[ii][3] += dc * v4.w;
            }
        }
#pragma unroll
        for (int ii = 0; ii < 5; ii++) {
            int i = ig * 5 + ii;
#pragma unroll
            for (int dd = 0; dd < 4; dd++) {
                int d = dg * 4 + dd;
                eo_out[(((size_t)n * DIMC + h * HD + d) * TT + t) * VV + i] = aE[ii][dd];
                sm[OXO + i * P + d] = aX[ii][dd];
            }
        }
    }
    // proj weights -> smem (vectorized; region reuse over dead Q/EQ/EK)
    for (int l4 = tid; l4 < 1024; l4 += 128)
        *(float4*)&sm[OW + l4 * 4] = *(const float4*)&proj_w[(size_t)h * 4096 + l4 * 4];
    __syncthreads();

    // ---- grouped projection ----
    if (tid < 80) {
        int ig = tid / 16;
        int og = tid % 16;
        float acc[5][4];
#pragma unroll
        for (int ii = 0; ii < 5; ii++)
#pragma unroll
            for (int oo = 0; oo < 4; oo++) acc[ii][oo] = 0.f;
#pragma unroll
        for (int c = 0; c < 64; c += 4) {
            float4 w4[4];
#pragma unroll
            for (int oo = 0; oo < 4; oo++)
                w4[oo] = *reinterpret_cast<const float4*>(&sm[OW + (og * 4 + oo) * 64 + c]);
#pragma unroll
            for (int ii = 0; ii < 5; ii++) {
                float4 x4 = *reinterpret_cast<const float4*>(&sm[OXO + (ig * 5 + ii) * P + c]);
#pragma unroll
                for (int oo = 0; oo < 4; oo++)
                    acc[ii][oo] += x4.x * w4[oo].x + x4.y * w4[oo].y
                                 + x4.z * w4[oo].z + x4.w * w4[oo].w;
            }
        }
#pragma unroll
        for (int oo = 0; oo < 4; oo++) {
            int o = og * 4 + oo;
            float b = __ldg(proj_b + h * HD + o);
#pragma unroll
            for (int ii = 0; ii < 5; ii++) {
                int i = ig * 5 + ii;
                xo_out[(((size_t)n * DIMC + h * HD + o) * TT + t) * VV + i] = acc[ii][oo] + b;
            }
        }
    }
}

extern "C" void kernel_launch(void* const* d_in, const int* in_sizes, int n_in,
                              void* d_out, int out_size)
{
    const float* x      = (const float*)d_in[0];
    const float* e      = (const float*)d_in[1];
    const float* kv_w   = (const float*)d_in[2];
    const float* q_w    = (const float*)d_in[3];
    const float* e_kv_w = (const float*)d_in[4];
    const float* e_q_w  = (const float*)d_in[5];
    const float* rpe    = (const float*)d_in[6];
    const float* outerp = (const float*)d_in[7];
    const float* alpha  = (const float*)d_in[8];
    const float* beta   = (const float*)d_in[9];
    const float* proj_w = (const float*)d_in[10];
    const float* proj_b = (const float*)d_in[11];
    const int*   hops   = (const int*)d_in[12];

    int nh = in_sizes[6] / DIMC;

    float* xo = (float*)d_out;
    float* eo = xo + (size_t)NB * DIMC * TT * VV;

    presplit_w<<<(1920 * 384 / 4 + 255) / 256, 256>>>(kv_w, q_w, e_kv_w, e_q_w);
    presplit_x<<<dim3(DIMC, NB, 2), 256>>>(x, e);

    cudaFuncSetAttribute(proj_mma, cudaFuncAttributeMaxDynamicSharedMemorySize, DYN_BYTES);
    proj_mma<<<dim3(13, 15, NB), 256, DYN_BYTES>>>();
    attn_kernel<<<dim3(HH, TT, NB), 128>>>(rpe, outerp, alpha, beta,
                                           proj_w, proj_b, hops, nh, xo, eo);
}